// round 3
// baseline (speedup 1.0000x reference)
#include <cuda_runtime.h>
#include <math.h>

constexpr int NB = 32;     // batch
constexpr int NC = 1024;   // channels
constexpr int NS = 1024;   // H*W
constexpr size_t MAT = (size_t)NC * NS;   // 1M elems per per-batch matrix

// Scratch (device globals — allocation-guard safe)
__device__ float g_q [(size_t)NB * MAT];
__device__ float g_k [(size_t)NB * MAT];
__device__ float g_v [(size_t)NB * MAT];
__device__ float g_s [(size_t)NB * MAT];   // scores -> weights (softmax in place)
__device__ float g_nv[(size_t)NB * MAT];

// ---------------------------------------------------------------------------
// Tiled SGEMM: C[b] = epilogue(A(b?) * B[b])
//   All dims are 1024. BM=BN=128, BK=8, 256 threads, 8x8 per-thread tile.
//   EPI: 0 = alpha*x ; 1 = tanh(x + bias[row]) ; 2 = x + bias[row] + resid
//   TRANSB: B operand stored row-major [N,K] (accessed transposed)
//   ABATCH: A operand is per-batch (q / weights) vs shared weight matrix
// ---------------------------------------------------------------------------
template<int EPI, bool TRANSB, bool ABATCH>
__global__ __launch_bounds__(256) void gemm_k(
    const float* __restrict__ A, const float* __restrict__ Bm,
    const float* __restrict__ bias, const float* __restrict__ resid,
    float* __restrict__ Cm, float alpha)
{
    __shared__ float As[8][128];
    __shared__ float Bs[8][128];

    const int tid = threadIdx.x;
    const int bx = blockIdx.x, by = blockIdx.y, bz = blockIdx.z;
    const size_t batOff = (size_t)bz * MAT;
    const float* Ab = ABATCH ? (A + batOff) : A;
    const float* Bb = Bm + batOff;
    float*       Cb = Cm + batOff;

    // A-tile loader: 128 rows x 8 k, one float4 along k per thread
    const int arow = tid >> 1;          // 0..127
    const int acol = (tid & 1) << 2;    // 0 or 4
    // B-tile loader (NN): 8 k-rows x 128 n, one float4 along n per thread
    const int brow = tid >> 5;          // 0..7
    const int bcol = (tid & 31) << 2;   // 0..124

    const int ty = tid >> 4, tx = tid & 15;

    float acc[8][8];
    #pragma unroll
    for (int i = 0; i < 8; ++i)
        #pragma unroll
        for (int j = 0; j < 8; ++j) acc[i][j] = 0.f;

    for (int k0 = 0; k0 < NC; k0 += 8) {
        float4 av = *(const float4*)(Ab + (size_t)(by * 128 + arow) * NC + k0 + acol);
        As[acol + 0][arow] = av.x;
        As[acol + 1][arow] = av.y;
        As[acol + 2][arow] = av.z;
        As[acol + 3][arow] = av.w;
        if (TRANSB) {
            // B row-major [N,K]: read 4 along k, scatter-transpose into Bs
            float4 bv = *(const float4*)(Bb + (size_t)(bx * 128 + arow) * NC + k0 + acol);
            Bs[acol + 0][arow] = bv.x;
            Bs[acol + 1][arow] = bv.y;
            Bs[acol + 2][arow] = bv.z;
            Bs[acol + 3][arow] = bv.w;
        } else {
            *(float4*)&Bs[brow][bcol] =
                *(const float4*)(Bb + (size_t)(k0 + brow) * NS + bx * 128 + bcol);
        }
        __syncthreads();

        #pragma unroll
        for (int kk = 0; kk < 8; ++kk) {
            float a[8], b[8];
            *(float4*)&a[0] = *(const float4*)&As[kk][ty * 8 + 0];
            *(float4*)&a[4] = *(const float4*)&As[kk][ty * 8 + 4];
            *(float4*)&b[0] = *(const float4*)&Bs[kk][tx * 8 + 0];
            *(float4*)&b[4] = *(const float4*)&Bs[kk][tx * 8 + 4];
            #pragma unroll
            for (int i = 0; i < 8; ++i)
                #pragma unroll
                for (int j = 0; j < 8; ++j)
                    acc[i][j] = fmaf(a[i], b[j], acc[i][j]);
        }
        __syncthreads();
    }

    const int row0 = by * 128 + ty * 8;
    const int col0 = bx * 128 + tx * 8;
    #pragma unroll
    for (int i = 0; i < 8; ++i) {
        const size_t rbase = (size_t)(row0 + i) * NS + col0;
        float bi = (EPI >= 1) ? bias[row0 + i] : 0.f;
        #pragma unroll
        for (int j = 0; j < 8; ++j) {
            float v = acc[i][j];
            if (EPI == 0)      v *= alpha;
            else if (EPI == 1) v = tanhf(v + bi);
            else               v = v + bi + resid[batOff + rbase + j];
            Cb[rbase + j] = v;
        }
    }
}

// ---------------------------------------------------------------------------
// Row softmax (in place): 1024 cols per row, one block of 256 threads per row
// ---------------------------------------------------------------------------
__global__ __launch_bounds__(256) void softmax_k(float* __restrict__ data)
{
    __shared__ float red[8];
    __shared__ float bval;
    const size_t row = blockIdx.x;
    float* p = data + row * (size_t)NC;
    const int tid  = threadIdx.x;
    const int lane = tid & 31, wid = tid >> 5;

    float4 v = ((float4*)p)[tid];

    // --- max ---
    float m = fmaxf(fmaxf(v.x, v.y), fmaxf(v.z, v.w));
    #pragma unroll
    for (int o = 16; o > 0; o >>= 1) m = fmaxf(m, __shfl_xor_sync(0xffffffffu, m, o));
    if (lane == 0) red[wid] = m;
    __syncthreads();
    if (tid < 32) {
        float t = (tid < 8) ? red[tid] : -INFINITY;
        #pragma unroll
        for (int o = 4; o > 0; o >>= 1) t = fmaxf(t, __shfl_xor_sync(0xffffffffu, t, o));
        if (tid == 0) bval = t;
    }
    __syncthreads();
    m = bval;

    // --- exp + sum ---
    v.x = expf(v.x - m); v.y = expf(v.y - m);
    v.z = expf(v.z - m); v.w = expf(v.w - m);
    float s = (v.x + v.y) + (v.z + v.w);
    #pragma unroll
    for (int o = 16; o > 0; o >>= 1) s += __shfl_xor_sync(0xffffffffu, s, o);
    __syncthreads();                       // red[] reuse barrier
    if (lane == 0) red[wid] = s;
    __syncthreads();
    if (tid < 32) {
        float t = (tid < 8) ? red[tid] : 0.f;
        #pragma unroll
        for (int o = 4; o > 0; o >>= 1) t += __shfl_xor_sync(0xffffffffu, t, o);
        if (tid == 0) bval = t;
    }
    __syncthreads();
    const float inv = 1.f / bval;
    v.x *= inv; v.y *= inv; v.z *= inv; v.w *= inv;
    ((float4*)p)[tid] = v;
}

// ---------------------------------------------------------------------------
extern "C" void kernel_launch(void* const* d_in, const int* in_sizes, int n_in,
                              void* d_out, int out_size)
{
    const float* shape_map = (const float*)d_in[0];
    const float* img_map   = (const float*)d_in[1];
    const float* wq = (const float*)d_in[2];
    const float* bq = (const float*)d_in[3];
    const float* wk = (const float*)d_in[4];
    const float* bk = (const float*)d_in[5];
    const float* wv = (const float*)d_in[6];
    const float* bv = (const float*)d_in[7];
    const float* wc = (const float*)d_in[8];
    const float* bc = (const float*)d_in[9];
    float* out = (float*)d_out;

    float *q, *k, *v, *s, *nv;
    cudaGetSymbolAddress((void**)&q,  g_q);
    cudaGetSymbolAddress((void**)&k,  g_k);
    cudaGetSymbolAddress((void**)&v,  g_v);
    cudaGetSymbolAddress((void**)&s,  g_s);
    cudaGetSymbolAddress((void**)&nv, g_nv);

    const dim3 grid(NS / 128, NC / 128, NB);   // (8, 8, 32)

    // Q = tanh(Wq @ shape + bq), K = tanh(Wk @ img + bk), V = tanh(Wv @ img + bv)
    gemm_k<1, false, false><<<grid, 256>>>(wq, shape_map, bq, nullptr, q, 0.f);
    gemm_k<1, false, false><<<grid, 256>>>(wk, img_map,   bk, nullptr, k, 0.f);
    gemm_k<1, false, false><<<grid, 256>>>(wv, img_map,   bv, nullptr, v, 0.f);

    // scores = (Q @ K^T) / sqrt(C)
    gemm_k<0, true, true><<<grid, 256>>>(q, k, nullptr, nullptr, s, 0.03125f);

    // softmax over last dim
    softmax_k<<<NB * NC, 256>>>(s);

    // new_v = weights @ V
    gemm_k<0, false, true><<<grid, 256>>>(s, v, nullptr, nullptr, nv, 1.f);

    // out = Wc @ new_v + bc + shape_map
    gemm_k<2, false, false><<<grid, 256>>>(wc, nv, bc, shape_map, out, 0.f);
}

// round 5
// speedup vs baseline: 2.3413x; 2.3413x over previous
#include <cuda_runtime.h>
#include <cuda_bf16.h>
#include <cstdint>
#include <math.h>

constexpr int NB = 32;
constexpr int NC = 1024;
constexpr int NS = 1024;
constexpr size_t MAT = (size_t)NC * NS;           // 1M elems
constexpr size_t MB1 = 1u << 20;

// ---------------------------------------------------------------------------
// One big scratch buffer (device global — allocation-guard safe)
// ---------------------------------------------------------------------------
__device__ __align__(128) unsigned char g_buf[1040 * MB1];

#define OFF_XSH   (0 * 64 * MB1)
#define OFF_XSL   (1 * 64 * MB1)
#define OFF_XIH   (2 * 64 * MB1)
#define OFF_XIL   (3 * 64 * MB1)
#define OFF_QH    (4 * 64 * MB1)
#define OFF_QL    (5 * 64 * MB1)
#define OFF_KH    (6 * 64 * MB1)
#define OFF_KL    (7 * 64 * MB1)
#define OFF_VTH   (8 * 64 * MB1)
#define OFF_VTL   (9 * 64 * MB1)
#define OFF_WAH   (10 * 64 * MB1)
#define OFF_WAL   (11 * 64 * MB1)
#define OFF_NVTH  (12 * 64 * MB1)
#define OFF_NVTL  (13 * 64 * MB1)
#define OFF_SF32  (14 * 64 * MB1)                 // 128MB fp32 scores
#define OFF_W0    (16 * 64 * MB1)                 // 8 x 2MB weight hi/lo

// ---------------------------------------------------------------------------
// sm_80+-portable PTX helpers (NO tcgen05 — unavailable via compute_103 PTX)
// ---------------------------------------------------------------------------
__device__ __forceinline__ uint32_t smem_to_u32(const void* p) {
    uint32_t a;
    asm("{ .reg .u64 t; cvta.to.shared.u64 t, %1; cvt.u32.u64 %0, t; }" : "=r"(a) : "l"(p));
    return a;
}
__device__ __forceinline__ void cp16(uint32_t dst, const void* src) {
    asm volatile("cp.async.cg.shared.global [%0], [%1], 16;" :: "r"(dst), "l"(src) : "memory");
}
__device__ __forceinline__ void ldsm4(uint32_t* r, uint32_t addr) {
    asm volatile("ldmatrix.sync.aligned.m8n8.x4.shared.b16 {%0,%1,%2,%3}, [%4];"
        : "=r"(r[0]), "=r"(r[1]), "=r"(r[2]), "=r"(r[3]) : "r"(addr));
}
__device__ __forceinline__ void mma_bf16(float* c, const uint32_t* a, const uint32_t* b) {
    asm volatile(
        "mma.sync.aligned.m16n8k16.row.col.f32.bf16.bf16.f32 "
        "{%0,%1,%2,%3}, {%4,%5,%6,%7}, {%8,%9}, {%0,%1,%2,%3};"
        : "+f"(c[0]), "+f"(c[1]), "+f"(c[2]), "+f"(c[3])
        : "r"(a[0]), "r"(a[1]), "r"(a[2]), "r"(a[3]), "r"(b[0]), "r"(b[1]));
}

__device__ __forceinline__ void split_bf16(float v, __nv_bfloat16& h, __nv_bfloat16& l) {
    h = __float2bfloat16(v);
    l = __float2bfloat16(v - __bfloat162float(h));
}

enum { EPI_TANH = 0, EPI_TANH_T = 1, EPI_SCALE = 2, EPI_SPLIT_T = 3, EPI_BIASRES = 4 };

// GEMM tiling
constexpr int STAGES = 3;
constexpr int BK = 32;
constexpr int CHUNKS = NC / BK;                    // 32
constexpr int TPAD = 40;                           // padded row (bf16 elems)
constexpr int TILE_BYTES = 128 * TPAD * 2;         // 10240
constexpr int STAGE_BYTES = 4 * TILE_BYTES;        // 40960
constexpr int SMEM_BYTES = STAGES * STAGE_BYTES;   // 122880

// ---------------------------------------------------------------------------
// Split-bf16 mma.sync GEMM:  D[m,n] = sum_k A[m,k]*B[n,k]  (both K-major)
// CTA 128x128, warp 64x32, BK=32, 3-stage cp.async pipeline, fused epilogues.
// ---------------------------------------------------------------------------
template<int EPI, bool ABATCH>
__global__ __launch_bounds__(256, 1) void gemm_mma(
    const __nv_bfloat16* __restrict__ Ah, const __nv_bfloat16* __restrict__ Al,
    const __nv_bfloat16* __restrict__ Bh, const __nv_bfloat16* __restrict__ Bl,
    const float* __restrict__ bias, const float* __restrict__ resid,
    float* __restrict__ Of, __nv_bfloat16* __restrict__ Oh, __nv_bfloat16* __restrict__ Ol,
    float alpha)
{
    extern __shared__ char smem[];
    const uint32_t sb = smem_to_u32(smem);
    const int tid = threadIdx.x, lane = tid & 31, wid = tid >> 5;
    const int warp_m = wid & 1, warp_n = wid >> 1;
    const int bx = blockIdx.x, by = blockIdx.y, bz = blockIdx.z;
    const size_t bat = (size_t)bz * MAT;
    const int m0 = by * 128, n0 = bx * 128;

    const __nv_bfloat16* srcA_h = Ah + (ABATCH ? bat : 0);
    const __nv_bfloat16* srcA_l = Al + (ABATCH ? bat : 0);
    const __nv_bfloat16* srcB_h = Bh + bat;
    const __nv_bfloat16* srcB_l = Bl + bat;

    auto load_chunk = [&](int chunk, int stage) {
        const int k0 = chunk * BK;
        const uint32_t sbase = sb + stage * STAGE_BYTES;
        const __nv_bfloat16* srcs[4] = { srcA_h, srcA_l, srcB_h, srcB_l };
        const int r0s[4] = { m0, m0, n0, n0 };
        #pragma unroll
        for (int tl = 0; tl < 4; ++tl) {
            #pragma unroll
            for (int t = 0; t < 2; ++t) {
                int gi = tid + t * 256;                 // 0..511
                int r = gi >> 2, c8 = (gi & 3) * 8;
                cp16(sbase + (uint32_t)(tl * TILE_BYTES) + (uint32_t)(r * TPAD + c8) * 2,
                     srcs[tl] + (size_t)(r0s[tl] + r) * 1024 + k0 + c8);
            }
        }
    };

    // prologue: stages 0,1
    load_chunk(0, 0);
    asm volatile("cp.async.commit_group;" ::: "memory");
    load_chunk(1, 1);
    asm volatile("cp.async.commit_group;" ::: "memory");

    float acc[4][4][4];
    #pragma unroll
    for (int mi = 0; mi < 4; ++mi)
        #pragma unroll
        for (int ni = 0; ni < 4; ++ni)
            #pragma unroll
            for (int e = 0; e < 4; ++e) acc[mi][ni][e] = 0.f;

    for (int c = 0; c < CHUNKS; ++c) {
        asm volatile("cp.async.wait_group 1;" ::: "memory");   // STAGES-2
        __syncthreads();

        const int nc = c + STAGES - 1;
        if (nc < CHUNKS) load_chunk(nc, nc % STAGES);
        asm volatile("cp.async.commit_group;" ::: "memory");

        const uint32_t sbase = sb + (c % STAGES) * STAGE_BYTES;
        const uint32_t aHb = sbase + 0 * TILE_BYTES, aLb = sbase + 1 * TILE_BYTES;
        const uint32_t bHb = sbase + 2 * TILE_BYTES, bLb = sbase + 3 * TILE_BYTES;

        #pragma unroll
        for (int s16 = 0; s16 < 2; ++s16) {
            const int koff = s16 * 16;
            uint32_t ah[4][4], al[4][4], bh[2][4], bl[2][4];
            #pragma unroll
            for (int mi = 0; mi < 4; ++mi) {
                uint32_t ro = (uint32_t)((warp_m * 64 + mi * 16 + (lane & 15)) * TPAD) * 2
                            + (uint32_t)(koff + ((lane >> 4) << 3)) * 2;
                ldsm4(ah[mi], aHb + ro);
                ldsm4(al[mi], aLb + ro);
            }
            #pragma unroll
            for (int nj = 0; nj < 2; ++nj) {
                uint32_t ro = (uint32_t)((warp_n * 32 + nj * 16 + (lane & 7) + ((lane >> 4) << 3)) * TPAD) * 2
                            + (uint32_t)(koff + (((lane >> 3) & 1) << 3)) * 2;
                ldsm4(bh[nj], bHb + ro);
                ldsm4(bl[nj], bLb + ro);
            }
            #pragma unroll
            for (int mi = 0; mi < 4; ++mi)
                #pragma unroll
                for (int ni = 0; ni < 4; ++ni) {
                    const uint32_t* bhp = &bh[ni >> 1][(ni & 1) * 2];
                    const uint32_t* blp = &bl[ni >> 1][(ni & 1) * 2];
                    mma_bf16(acc[mi][ni], ah[mi], bhp);
                    mma_bf16(acc[mi][ni], ah[mi], blp);
                    mma_bf16(acc[mi][ni], al[mi], bhp);
                }
        }
    }

    // ------------------------------ epilogue -------------------------------
    const int erow = m0 + warp_m * 64;
    const int ecol = n0 + warp_n * 32;
    const int rl = lane >> 2, cl = (lane & 3) * 2;

    #pragma unroll
    for (int mi = 0; mi < 4; ++mi) {
        const int r0e = erow + mi * 16 + rl;           // rows r0e, r0e+8
        float b0 = 0.f, b1 = 0.f;
        if (EPI == EPI_TANH || EPI == EPI_TANH_T || EPI == EPI_BIASRES) {
            b0 = bias[r0e]; b1 = bias[r0e + 8];
        }
        #pragma unroll
        for (int ni = 0; ni < 4; ++ni) {
            const int c0e = ecol + ni * 8 + cl;
            float* a = acc[mi][ni];

            if (EPI == EPI_TANH) {
                float v00 = tanhf(a[0] + b0), v01 = tanhf(a[1] + b0);
                float v10 = tanhf(a[2] + b1), v11 = tanhf(a[3] + b1);
                __nv_bfloat16 h0, l0, h1, l1;
                split_bf16(v00, h0, l0); split_bf16(v01, h1, l1);
                __nv_bfloat162 ph{h0, h1}, pl{l0, l1};
                *(__nv_bfloat162*)(Oh + bat + (size_t)r0e * 1024 + c0e) = ph;
                *(__nv_bfloat162*)(Ol + bat + (size_t)r0e * 1024 + c0e) = pl;
                split_bf16(v10, h0, l0); split_bf16(v11, h1, l1);
                __nv_bfloat162 ph2{h0, h1}, pl2{l0, l1};
                *(__nv_bfloat162*)(Oh + bat + (size_t)(r0e + 8) * 1024 + c0e) = ph2;
                *(__nv_bfloat162*)(Ol + bat + (size_t)(r0e + 8) * 1024 + c0e) = pl2;
            } else if (EPI == EPI_TANH_T || EPI == EPI_SPLIT_T) {
                float v[4] = { a[0], a[1], a[2], a[3] };
                if (EPI == EPI_TANH_T) {
                    v[0] = tanhf(v[0] + b0); v[1] = tanhf(v[1] + b0);
                    v[2] = tanhf(v[2] + b1); v[3] = tanhf(v[3] + b1);
                }
                const int rr[4] = { r0e, r0e, r0e + 8, r0e + 8 };
                const int cc[4] = { c0e, c0e + 1, c0e, c0e + 1 };
                #pragma unroll
                for (int e = 0; e < 4; ++e) {
                    __nv_bfloat16 hh, ll;
                    split_bf16(v[e], hh, ll);
                    const size_t idx = bat + (size_t)cc[e] * 1024 + rr[e];
                    Oh[idx] = hh; Ol[idx] = ll;
                }
            } else if (EPI == EPI_SCALE) {
                float2 o0{a[0] * alpha, a[1] * alpha};
                float2 o1{a[2] * alpha, a[3] * alpha};
                *(float2*)(Of + bat + (size_t)r0e * 1024 + c0e) = o0;
                *(float2*)(Of + bat + (size_t)(r0e + 8) * 1024 + c0e) = o1;
            } else {  // EPI_BIASRES
                float2 r0v = *(const float2*)(resid + bat + (size_t)r0e * 1024 + c0e);
                float2 r1v = *(const float2*)(resid + bat + (size_t)(r0e + 8) * 1024 + c0e);
                float2 o0{a[0] + b0 + r0v.x, a[1] + b0 + r0v.y};
                float2 o1{a[2] + b1 + r1v.x, a[3] + b1 + r1v.y};
                *(float2*)(Of + bat + (size_t)r0e * 1024 + c0e) = o0;
                *(float2*)(Of + bat + (size_t)(r0e + 8) * 1024 + c0e) = o1;
            }
        }
    }
}

// ---------------------------------------------------------------------------
// fp32 -> bf16 hi/lo elementwise (weights)
// ---------------------------------------------------------------------------
__global__ __launch_bounds__(256) void split_k(const float* __restrict__ in,
                                               __nv_bfloat16* __restrict__ oh,
                                               __nv_bfloat16* __restrict__ ol) {
    size_t i = (size_t)blockIdx.x * 256 + threadIdx.x;
    float v = in[i];
    __nv_bfloat16 h, l;
    split_bf16(v, h, l);
    oh[i] = h; ol[i] = l;
}

// ---------------------------------------------------------------------------
// fp32 [B][C,S] -> transposed bf16 hi/lo [B][S,C]
// ---------------------------------------------------------------------------
__global__ __launch_bounds__(256) void transpose_split_k(
    const float* __restrict__ in, __nv_bfloat16* __restrict__ oh, __nv_bfloat16* __restrict__ ol) {
    __shared__ float t[32][33];
    const int tx = threadIdx.x, ty = threadIdx.y;   // 32x8
    const int s0 = blockIdx.x * 32, c0 = blockIdx.y * 32;
    const size_t bat = (size_t)blockIdx.z * MAT;
    #pragma unroll
    for (int i = 0; i < 4; ++i)
        t[ty + 8 * i][tx] = in[bat + (size_t)(c0 + ty + 8 * i) * 1024 + s0 + tx];
    __syncthreads();
    #pragma unroll
    for (int i = 0; i < 4; ++i) {
        float v = t[tx][ty + 8 * i];
        __nv_bfloat16 h, l;
        split_bf16(v, h, l);
        const size_t idx = bat + (size_t)(s0 + ty + 8 * i) * 1024 + c0 + tx;
        oh[idx] = h; ol[idx] = l;
    }
}

// ---------------------------------------------------------------------------
// Row softmax fp32 -> bf16 hi/lo weights
// ---------------------------------------------------------------------------
__global__ __launch_bounds__(256) void softmax_split_k(
    const float* __restrict__ data, __nv_bfloat16* __restrict__ oh, __nv_bfloat16* __restrict__ ol) {
    __shared__ float red[8];
    __shared__ float bval;
    const size_t row = blockIdx.x;
    const float* p = data + row * (size_t)NC;
    const int tid = threadIdx.x, lane = tid & 31, wid = tid >> 5;

    float4 v = ((const float4*)p)[tid];
    float mx = fmaxf(fmaxf(v.x, v.y), fmaxf(v.z, v.w));
    #pragma unroll
    for (int o = 16; o > 0; o >>= 1) mx = fmaxf(mx, __shfl_xor_sync(0xffffffffu, mx, o));
    if (lane == 0) red[wid] = mx;
    __syncthreads();
    if (tid < 32) {
        float t = (tid < 8) ? red[tid] : -INFINITY;
        #pragma unroll
        for (int o = 4; o > 0; o >>= 1) t = fmaxf(t, __shfl_xor_sync(0xffffffffu, t, o));
        if (tid == 0) bval = t;
    }
    __syncthreads();
    mx = bval;
    v.x = expf(v.x - mx); v.y = expf(v.y - mx);
    v.z = expf(v.z - mx); v.w = expf(v.w - mx);
    float s = (v.x + v.y) + (v.z + v.w);
    #pragma unroll
    for (int o = 16; o > 0; o >>= 1) s += __shfl_xor_sync(0xffffffffu, s, o);
    __syncthreads();
    if (lane == 0) red[wid] = s;
    __syncthreads();
    if (tid < 32) {
        float t = (tid < 8) ? red[tid] : 0.f;
        #pragma unroll
        for (int o = 4; o > 0; o >>= 1) t += __shfl_xor_sync(0xffffffffu, t, o);
        if (tid == 0) bval = t;
    }
    __syncthreads();
    const float inv = 1.f / bval;
    float vv[4] = {v.x * inv, v.y * inv, v.z * inv, v.w * inv};
    const size_t base = row * (size_t)NC + 4 * tid;
    #pragma unroll
    for (int j = 0; j < 4; ++j) {
        __nv_bfloat16 h, l;
        split_bf16(vv[j], h, l);
        oh[base + j] = h; ol[base + j] = l;
    }
}

// ---------------------------------------------------------------------------
extern "C" void kernel_launch(void* const* d_in, const int* in_sizes, int n_in,
                              void* d_out, int out_size)
{
    const float* shape_map = (const float*)d_in[0];
    const float* img_map   = (const float*)d_in[1];
    const float* wq = (const float*)d_in[2];
    const float* bq = (const float*)d_in[3];
    const float* wk = (const float*)d_in[4];
    const float* bk = (const float*)d_in[5];
    const float* wv = (const float*)d_in[6];
    const float* bv = (const float*)d_in[7];
    const float* wc = (const float*)d_in[8];
    const float* bc = (const float*)d_in[9];
    float* out = (float*)d_out;

    unsigned char* buf;
    cudaGetSymbolAddress((void**)&buf, g_buf);
    __nv_bfloat16* XSH = (__nv_bfloat16*)(buf + OFF_XSH);
    __nv_bfloat16* XSL = (__nv_bfloat16*)(buf + OFF_XSL);
    __nv_bfloat16* XIH = (__nv_bfloat16*)(buf + OFF_XIH);
    __nv_bfloat16* XIL = (__nv_bfloat16*)(buf + OFF_XIL);
    __nv_bfloat16* QH  = (__nv_bfloat16*)(buf + OFF_QH);
    __nv_bfloat16* QL  = (__nv_bfloat16*)(buf + OFF_QL);
    __nv_bfloat16* KH  = (__nv_bfloat16*)(buf + OFF_KH);
    __nv_bfloat16* KL  = (__nv_bfloat16*)(buf + OFF_KL);
    __nv_bfloat16* VTH = (__nv_bfloat16*)(buf + OFF_VTH);
    __nv_bfloat16* VTL = (__nv_bfloat16*)(buf + OFF_VTL);
    __nv_bfloat16* WAH = (__nv_bfloat16*)(buf + OFF_WAH);
    __nv_bfloat16* WAL = (__nv_bfloat16*)(buf + OFF_WAL);
    __nv_bfloat16* NVTH = (__nv_bfloat16*)(buf + OFF_NVTH);
    __nv_bfloat16* NVTL = (__nv_bfloat16*)(buf + OFF_NVTL);
    float* SF = (float*)(buf + OFF_SF32);
    __nv_bfloat16* W[8];   // qh,ql,kh,kl,vh,vl,ch,cl
    for (int i = 0; i < 8; ++i) W[i] = (__nv_bfloat16*)(buf + OFF_W0 + (size_t)i * 2 * MB1);

    cudaFuncSetAttribute(gemm_mma<EPI_TANH, false>,   cudaFuncAttributeMaxDynamicSharedMemorySize, SMEM_BYTES);
    cudaFuncSetAttribute(gemm_mma<EPI_TANH_T, false>, cudaFuncAttributeMaxDynamicSharedMemorySize, SMEM_BYTES);
    cudaFuncSetAttribute(gemm_mma<EPI_SCALE, true>,   cudaFuncAttributeMaxDynamicSharedMemorySize, SMEM_BYTES);
    cudaFuncSetAttribute(gemm_mma<EPI_SPLIT_T, true>, cudaFuncAttributeMaxDynamicSharedMemorySize, SMEM_BYTES);
    cudaFuncSetAttribute(gemm_mma<EPI_BIASRES, false>,cudaFuncAttributeMaxDynamicSharedMemorySize, SMEM_BYTES);

    // 1) convert weights + transpose-convert inputs to bf16 hi/lo
    split_k<<<MAT / 256, 256>>>(wq, W[0], W[1]);
    split_k<<<MAT / 256, 256>>>(wk, W[2], W[3]);
    split_k<<<MAT / 256, 256>>>(wv, W[4], W[5]);
    split_k<<<MAT / 256, 256>>>(wc, W[6], W[7]);
    transpose_split_k<<<dim3(32, 32, NB), dim3(32, 8)>>>(shape_map, XSH, XSL);
    transpose_split_k<<<dim3(32, 32, NB), dim3(32, 8)>>>(img_map, XIH, XIL);

    const dim3 grid(8, 8, NB);
    // 2) Q = tanh(Wq@X + bq) [C,S]; K likewise; V stored transposed [S,C]
    gemm_mma<EPI_TANH, false><<<grid, 256, SMEM_BYTES>>>(W[0], W[1], XSH, XSL, bq, nullptr, nullptr, QH, QL, 0.f);
    gemm_mma<EPI_TANH, false><<<grid, 256, SMEM_BYTES>>>(W[2], W[3], XIH, XIL, bk, nullptr, nullptr, KH, KL, 0.f);
    gemm_mma<EPI_TANH_T, false><<<grid, 256, SMEM_BYTES>>>(W[4], W[5], XIH, XIL, bv, nullptr, nullptr, VTH, VTL, 0.f);
    // 3) scores = (Q @ K^T) / 32  -> fp32 [C,C]
    gemm_mma<EPI_SCALE, true><<<grid, 256, SMEM_BYTES>>>(QH, QL, KH, KL, nullptr, nullptr, SF, nullptr, nullptr, 0.03125f);
    // 4) softmax rows -> bf16 hi/lo weights
    softmax_split_k<<<NB * NC, 256>>>(SF, WAH, WAL);
    // 5) new_v = weights @ V  -> stored transposed [S,C]
    gemm_mma<EPI_SPLIT_T, true><<<grid, 256, SMEM_BYTES>>>(WAH, WAL, VTH, VTL, nullptr, nullptr, nullptr, NVTH, NVTL, 0.f);
    // 6) out = Wc @ new_v + bc + shape_map  -> fp32 [C,S]
    gemm_mma<EPI_BIASRES, false><<<grid, 256, SMEM_BYTES>>>(W[6], W[7], NVTH, NVTL, bc, shape_map, out, nullptr, nullptr, 0.f);
}

// round 6
// speedup vs baseline: 2.6710x; 1.1408x over previous
#include <cuda_runtime.h>
#include <cuda_bf16.h>
#include <cstdint>
#include <math.h>

constexpr int NB = 32;
constexpr int NC = 1024;
constexpr int NS = 1024;
constexpr size_t MAT = (size_t)NC * NS;           // 1M elems
constexpr size_t MB1 = 1u << 20;

// ---------------------------------------------------------------------------
// One big scratch buffer (device global — allocation-guard safe)
// ---------------------------------------------------------------------------
__device__ __align__(128) unsigned char g_buf[1040 * MB1];

#define OFF_XSH   (0 * 64 * MB1)
#define OFF_XSL   (1 * 64 * MB1)
#define OFF_XIH   (2 * 64 * MB1)
#define OFF_XIL   (3 * 64 * MB1)
#define OFF_QH    (4 * 64 * MB1)
#define OFF_QL    (5 * 64 * MB1)
#define OFF_KH    (6 * 64 * MB1)
#define OFF_KL    (7 * 64 * MB1)
#define OFF_VTH   (8 * 64 * MB1)
#define OFF_VTL   (9 * 64 * MB1)
#define OFF_WAH   (10 * 64 * MB1)
#define OFF_WAL   (11 * 64 * MB1)
#define OFF_NVTH  (12 * 64 * MB1)
#define OFF_NVTL  (13 * 64 * MB1)
#define OFF_SF32  (14 * 64 * MB1)                 // 128MB fp32 scores
#define OFF_W0    (16 * 64 * MB1)                 // 8 x 2MB weight hi/lo

// ---------------------------------------------------------------------------
// sm_80+-portable PTX helpers (NO tcgen05 — unavailable via compute_103 PTX)
// ---------------------------------------------------------------------------
__device__ __forceinline__ uint32_t smem_to_u32(const void* p) {
    uint32_t a;
    asm("{ .reg .u64 t; cvta.to.shared.u64 t, %1; cvt.u32.u64 %0, t; }" : "=r"(a) : "l"(p));
    return a;
}
__device__ __forceinline__ void cp16(uint32_t dst, const void* src) {
    asm volatile("cp.async.cg.shared.global [%0], [%1], 16;" :: "r"(dst), "l"(src) : "memory");
}
__device__ __forceinline__ void ldsm4(uint32_t* r, uint32_t addr) {
    asm volatile("ldmatrix.sync.aligned.m8n8.x4.shared.b16 {%0,%1,%2,%3}, [%4];"
        : "=r"(r[0]), "=r"(r[1]), "=r"(r[2]), "=r"(r[3]) : "r"(addr));
}
__device__ __forceinline__ void mma_bf16(float* c, const uint32_t* a, const uint32_t* b) {
    asm volatile(
        "mma.sync.aligned.m16n8k16.row.col.f32.bf16.bf16.f32 "
        "{%0,%1,%2,%3}, {%4,%5,%6,%7}, {%8,%9}, {%0,%1,%2,%3};"
        : "+f"(c[0]), "+f"(c[1]), "+f"(c[2]), "+f"(c[3])
        : "r"(a[0]), "r"(a[1]), "r"(a[2]), "r"(a[3]), "r"(b[0]), "r"(b[1]));
}

__device__ __forceinline__ void split_bf16(float v, __nv_bfloat16& h, __nv_bfloat16& l) {
    h = __float2bfloat16(v);
    l = __float2bfloat16(v - __bfloat162float(h));
}

enum { EPI_TANH = 0, EPI_TANH_T = 1, EPI_SCALE = 2, EPI_SPLIT_T = 3, EPI_BIASRES = 4 };

// GEMM tiling: CTA 128x128, BK=64, 3-stage pipeline
constexpr int STAGES = 3;
constexpr int BK = 64;
constexpr int CHUNKS = NC / BK;                    // 16
constexpr int TPAD = 72;                           // padded row (bf16 elems), 144B = 9*16B
constexpr int TILE_BYTES = 128 * TPAD * 2;         // 18432
constexpr int STAGE_BYTES = 4 * TILE_BYTES;        // 73728
constexpr int SMEM_BYTES = STAGES * STAGE_BYTES;   // 221184

// ---------------------------------------------------------------------------
// Split-bf16 mma.sync GEMM:  D[m,n] = sum_k A[m,k]*B[n,k]  (both K-major)
// ---------------------------------------------------------------------------
template<int EPI, bool ABATCH>
__global__ __launch_bounds__(256, 1) void gemm_mma(
    const __nv_bfloat16* __restrict__ Ah, const __nv_bfloat16* __restrict__ Al,
    const __nv_bfloat16* __restrict__ Bh, const __nv_bfloat16* __restrict__ Bl,
    const float* __restrict__ bias, const float* __restrict__ resid,
    float* __restrict__ Of, __nv_bfloat16* __restrict__ Oh, __nv_bfloat16* __restrict__ Ol,
    float alpha)
{
    extern __shared__ char smem[];
    const uint32_t sb = smem_to_u32(smem);
    const int tid = threadIdx.x, lane = tid & 31, wid = tid >> 5;
    const int warp_m = wid & 1, warp_n = wid >> 1;
    const int bx = blockIdx.x, by = blockIdx.y, bz = blockIdx.z;
    const size_t bat = (size_t)bz * MAT;
    const int m0 = by * 128, n0 = bx * 128;

    const __nv_bfloat16* srcA_h = Ah + (ABATCH ? bat : 0);
    const __nv_bfloat16* srcA_l = Al + (ABATCH ? bat : 0);
    const __nv_bfloat16* srcB_h = Bh + bat;
    const __nv_bfloat16* srcB_l = Bl + bat;

    auto load_chunk = [&](int chunk, int stage) {
        const int k0 = chunk * BK;
        const uint32_t sbase = sb + stage * STAGE_BYTES;
        const __nv_bfloat16* srcs[4] = { srcA_h, srcA_l, srcB_h, srcB_l };
        const int r0s[4] = { m0, m0, n0, n0 };
        #pragma unroll
        for (int tl = 0; tl < 4; ++tl) {
            #pragma unroll
            for (int t = 0; t < 4; ++t) {
                int gi = tid + t * 256;                 // 0..1023
                int r = gi >> 3, c8 = (gi & 7) * 8;
                cp16(sbase + (uint32_t)(tl * TILE_BYTES) + (uint32_t)(r * TPAD + c8) * 2,
                     srcs[tl] + (size_t)(r0s[tl] + r) * 1024 + k0 + c8);
            }
        }
    };

    // prologue: stages 0,1
    load_chunk(0, 0);
    asm volatile("cp.async.commit_group;" ::: "memory");
    load_chunk(1, 1);
    asm volatile("cp.async.commit_group;" ::: "memory");

    float acc[4][4][4];
    #pragma unroll
    for (int mi = 0; mi < 4; ++mi)
        #pragma unroll
        for (int ni = 0; ni < 4; ++ni)
            #pragma unroll
            for (int e = 0; e < 4; ++e) acc[mi][ni][e] = 0.f;

    for (int c = 0; c < CHUNKS; ++c) {
        asm volatile("cp.async.wait_group 1;" ::: "memory");   // chunk c arrived
        __syncthreads();

        const int nc = c + STAGES - 1;
        if (nc < CHUNKS) load_chunk(nc, nc % STAGES);
        asm volatile("cp.async.commit_group;" ::: "memory");

        const uint32_t sbase = sb + (c % STAGES) * STAGE_BYTES;
        const uint32_t aHb = sbase + 0 * TILE_BYTES, aLb = sbase + 1 * TILE_BYTES;
        const uint32_t bHb = sbase + 2 * TILE_BYTES, bLb = sbase + 3 * TILE_BYTES;

        #pragma unroll
        for (int s16 = 0; s16 < 4; ++s16) {
            const int koff = s16 * 16;
            uint32_t ah[4][4], al[4][4], bh[2][4], bl[2][4];
            #pragma unroll
            for (int mi = 0; mi < 4; ++mi) {
                uint32_t ro = (uint32_t)((warp_m * 64 + mi * 16 + (lane & 15)) * TPAD) * 2
                            + (uint32_t)(koff + ((lane >> 4) << 3)) * 2;
                ldsm4(ah[mi], aHb + ro);
                ldsm4(al[mi], aLb + ro);
            }
            #pragma unroll
            for (int nj = 0; nj < 2; ++nj) {
                uint32_t ro = (uint32_t)((warp_n * 32 + nj * 16 + (lane & 7) + ((lane >> 4) << 3)) * TPAD) * 2
                            + (uint32_t)(koff + (((lane >> 3) & 1) << 3)) * 2;
                ldsm4(bh[nj], bHb + ro);
                ldsm4(bl[nj], bLb + ro);
            }
            #pragma unroll
            for (int mi = 0; mi < 4; ++mi)
                #pragma unroll
                for (int ni = 0; ni < 4; ++ni) {
                    const uint32_t* bhp = &bh[ni >> 1][(ni & 1) * 2];
                    const uint32_t* blp = &bl[ni >> 1][(ni & 1) * 2];
                    mma_bf16(acc[mi][ni], ah[mi], bhp);
                    mma_bf16(acc[mi][ni], ah[mi], blp);
                    mma_bf16(acc[mi][ni], al[mi], bhp);
                }
        }
    }

    // ------------------------------ epilogue -------------------------------
    const int erow = m0 + warp_m * 64;
    const int ecol = n0 + warp_n * 32;
    const int rl = lane >> 2, cl = (lane & 3) * 2;

    #pragma unroll
    for (int mi = 0; mi < 4; ++mi) {
        const int r0e = erow + mi * 16 + rl;           // rows r0e, r0e+8
        float b0 = 0.f, b1 = 0.f;
        if (EPI == EPI_TANH || EPI == EPI_TANH_T || EPI == EPI_BIASRES) {
            b0 = bias[r0e]; b1 = bias[r0e + 8];
        }
        #pragma unroll
        for (int ni = 0; ni < 4; ++ni) {
            const int c0e = ecol + ni * 8 + cl;
            float* a = acc[mi][ni];

            if (EPI == EPI_TANH) {
                float v00 = tanhf(a[0] + b0), v01 = tanhf(a[1] + b0);
                float v10 = tanhf(a[2] + b1), v11 = tanhf(a[3] + b1);
                __nv_bfloat16 h0, l0, h1, l1;
                split_bf16(v00, h0, l0); split_bf16(v01, h1, l1);
                __nv_bfloat162 ph{h0, h1}, pl{l0, l1};
                *(__nv_bfloat162*)(Oh + bat + (size_t)r0e * 1024 + c0e) = ph;
                *(__nv_bfloat162*)(Ol + bat + (size_t)r0e * 1024 + c0e) = pl;
                split_bf16(v10, h0, l0); split_bf16(v11, h1, l1);
                __nv_bfloat162 ph2{h0, h1}, pl2{l0, l1};
                *(__nv_bfloat162*)(Oh + bat + (size_t)(r0e + 8) * 1024 + c0e) = ph2;
                *(__nv_bfloat162*)(Ol + bat + (size_t)(r0e + 8) * 1024 + c0e) = pl2;
            } else if (EPI == EPI_TANH_T || EPI == EPI_SPLIT_T) {
                float v[4] = { a[0], a[1], a[2], a[3] };
                if (EPI == EPI_TANH_T) {
                    v[0] = tanhf(v[0] + b0); v[1] = tanhf(v[1] + b0);
                    v[2] = tanhf(v[2] + b1); v[3] = tanhf(v[3] + b1);
                }
                const int rr[4] = { r0e, r0e, r0e + 8, r0e + 8 };
                const int cc[4] = { c0e, c0e + 1, c0e, c0e + 1 };
                #pragma unroll
                for (int e = 0; e < 4; ++e) {
                    __nv_bfloat16 hh, ll;
                    split_bf16(v[e], hh, ll);
                    const size_t idx = bat + (size_t)cc[e] * 1024 + rr[e];
                    Oh[idx] = hh; Ol[idx] = ll;
                }
            } else if (EPI == EPI_SCALE) {
                float2 o0{a[0] * alpha, a[1] * alpha};
                float2 o1{a[2] * alpha, a[3] * alpha};
                *(float2*)(Of + bat + (size_t)r0e * 1024 + c0e) = o0;
                *(float2*)(Of + bat + (size_t)(r0e + 8) * 1024 + c0e) = o1;
            } else {  // EPI_BIASRES
                float2 r0v = *(const float2*)(resid + bat + (size_t)r0e * 1024 + c0e);
                float2 r1v = *(const float2*)(resid + bat + (size_t)(r0e + 8) * 1024 + c0e);
                float2 o0{a[0] + b0 + r0v.x, a[1] + b0 + r0v.y};
                float2 o1{a[2] + b1 + r1v.x, a[3] + b1 + r1v.y};
                *(float2*)(Of + bat + (size_t)r0e * 1024 + c0e) = o0;
                *(float2*)(Of + bat + (size_t)(r0e + 8) * 1024 + c0e) = o1;
            }
        }
    }
}

// ---------------------------------------------------------------------------
// fp32 -> bf16 hi/lo elementwise (weights)
// ---------------------------------------------------------------------------
__global__ __launch_bounds__(256) void split_k(const float* __restrict__ in,
                                               __nv_bfloat16* __restrict__ oh,
                                               __nv_bfloat16* __restrict__ ol) {
    size_t i = (size_t)blockIdx.x * 256 + threadIdx.x;
    float v = in[i];
    __nv_bfloat16 h, l;
    split_bf16(v, h, l);
    oh[i] = h; ol[i] = l;
}

// ---------------------------------------------------------------------------
// fp32 [B][C,S] -> transposed bf16 hi/lo [B][S,C]
// ---------------------------------------------------------------------------
__global__ __launch_bounds__(256) void transpose_split_k(
    const float* __restrict__ in, __nv_bfloat16* __restrict__ oh, __nv_bfloat16* __restrict__ ol) {
    __shared__ float t[32][33];
    const int tx = threadIdx.x, ty = threadIdx.y;   // 32x8
    const int s0 = blockIdx.x * 32, c0 = blockIdx.y * 32;
    const size_t bat = (size_t)blockIdx.z * MAT;
    #pragma unroll
    for (int i = 0; i < 4; ++i)
        t[ty + 8 * i][tx] = in[bat + (size_t)(c0 + ty + 8 * i) * 1024 + s0 + tx];
    __syncthreads();
    #pragma unroll
    for (int i = 0; i < 4; ++i) {
        float v = t[tx][ty + 8 * i];
        __nv_bfloat16 h, l;
        split_bf16(v, h, l);
        const size_t idx = bat + (size_t)(s0 + ty + 8 * i) * 1024 + c0 + tx;
        oh[idx] = h; ol[idx] = l;
    }
}

// ---------------------------------------------------------------------------
// Row softmax fp32 -> bf16 hi/lo weights
// ---------------------------------------------------------------------------
__global__ __launch_bounds__(256) void softmax_split_k(
    const float* __restrict__ data, __nv_bfloat16* __restrict__ oh, __nv_bfloat16* __restrict__ ol) {
    __shared__ float red[8];
    __shared__ float bval;
    const size_t row = blockIdx.x;
    const float* p = data + row * (size_t)NC;
    const int tid = threadIdx.x, lane = tid & 31, wid = tid >> 5;

    float4 v = ((const float4*)p)[tid];
    float mx = fmaxf(fmaxf(v.x, v.y), fmaxf(v.z, v.w));
    #pragma unroll
    for (int o = 16; o > 0; o >>= 1) mx = fmaxf(mx, __shfl_xor_sync(0xffffffffu, mx, o));
    if (lane == 0) red[wid] = mx;
    __syncthreads();
    if (tid < 32) {
        float t = (tid < 8) ? red[tid] : -INFINITY;
        #pragma unroll
        for (int o = 4; o > 0; o >>= 1) t = fmaxf(t, __shfl_xor_sync(0xffffffffu, t, o));
        if (tid == 0) bval = t;
    }
    __syncthreads();
    mx = bval;
    v.x = expf(v.x - mx); v.y = expf(v.y - mx);
    v.z = expf(v.z - mx); v.w = expf(v.w - mx);
    float s = (v.x + v.y) + (v.z + v.w);
    #pragma unroll
    for (int o = 16; o > 0; o >>= 1) s += __shfl_xor_sync(0xffffffffu, s, o);
    __syncthreads();
    if (lane == 0) red[wid] = s;
    __syncthreads();
    if (tid < 32) {
        float t = (tid < 8) ? red[tid] : 0.f;
        #pragma unroll
        for (int o = 4; o > 0; o >>= 1) t += __shfl_xor_sync(0xffffffffu, t, o);
        if (tid == 0) bval = t;
    }
    __syncthreads();
    const float inv = 1.f / bval;
    float vv[4] = {v.x * inv, v.y * inv, v.z * inv, v.w * inv};
    const size_t base = row * (size_t)NC + 4 * tid;
    #pragma unroll
    for (int j = 0; j < 4; ++j) {
        __nv_bfloat16 h, l;
        split_bf16(vv[j], h, l);
        oh[base + j] = h; ol[base + j] = l;
    }
}

// ---------------------------------------------------------------------------
extern "C" void kernel_launch(void* const* d_in, const int* in_sizes, int n_in,
                              void* d_out, int out_size)
{
    const float* shape_map = (const float*)d_in[0];
    const float* img_map   = (const float*)d_in[1];
    const float* wq = (const float*)d_in[2];
    const float* bq = (const float*)d_in[3];
    const float* wk = (const float*)d_in[4];
    const float* bk = (const float*)d_in[5];
    const float* wv = (const float*)d_in[6];
    const float* bv = (const float*)d_in[7];
    const float* wc = (const float*)d_in[8];
    const float* bc = (const float*)d_in[9];
    float* out = (float*)d_out;

    unsigned char* buf;
    cudaGetSymbolAddress((void**)&buf, g_buf);
    __nv_bfloat16* XSH = (__nv_bfloat16*)(buf + OFF_XSH);
    __nv_bfloat16* XSL = (__nv_bfloat16*)(buf + OFF_XSL);
    __nv_bfloat16* XIH = (__nv_bfloat16*)(buf + OFF_XIH);
    __nv_bfloat16* XIL = (__nv_bfloat16*)(buf + OFF_XIL);
    __nv_bfloat16* QH  = (__nv_bfloat16*)(buf + OFF_QH);
    __nv_bfloat16* QL  = (__nv_bfloat16*)(buf + OFF_QL);
    __nv_bfloat16* KH  = (__nv_bfloat16*)(buf + OFF_KH);
    __nv_bfloat16* KL  = (__nv_bfloat16*)(buf + OFF_KL);
    __nv_bfloat16* VTH = (__nv_bfloat16*)(buf + OFF_VTH);
    __nv_bfloat16* VTL = (__nv_bfloat16*)(buf + OFF_VTL);
    __nv_bfloat16* WAH = (__nv_bfloat16*)(buf + OFF_WAH);
    __nv_bfloat16* WAL = (__nv_bfloat16*)(buf + OFF_WAL);
    __nv_bfloat16* NVTH = (__nv_bfloat16*)(buf + OFF_NVTH);
    __nv_bfloat16* NVTL = (__nv_bfloat16*)(buf + OFF_NVTL);
    float* SF = (float*)(buf + OFF_SF32);
    __nv_bfloat16* W[8];   // qh,ql,kh,kl,vh,vl,ch,cl
    for (int i = 0; i < 8; ++i) W[i] = (__nv_bfloat16*)(buf + OFF_W0 + (size_t)i * 2 * MB1);

    cudaFuncSetAttribute(gemm_mma<EPI_TANH, false>,   cudaFuncAttributeMaxDynamicSharedMemorySize, SMEM_BYTES);
    cudaFuncSetAttribute(gemm_mma<EPI_TANH_T, false>, cudaFuncAttributeMaxDynamicSharedMemorySize, SMEM_BYTES);
    cudaFuncSetAttribute(gemm_mma<EPI_SCALE, true>,   cudaFuncAttributeMaxDynamicSharedMemorySize, SMEM_BYTES);
    cudaFuncSetAttribute(gemm_mma<EPI_SPLIT_T, true>, cudaFuncAttributeMaxDynamicSharedMemorySize, SMEM_BYTES);
    cudaFuncSetAttribute(gemm_mma<EPI_BIASRES, false>,cudaFuncAttributeMaxDynamicSharedMemorySize, SMEM_BYTES);

    const dim3 grid(8, 8, NB);

    // Launch order arranged so ncu (-s 5 -c 1) captures a GEMM (launch #5 = gemm K).
    // 0..2: wq split, shape transpose, GEMM Q
    split_k<<<MAT / 256, 256>>>(wq, W[0], W[1]);
    transpose_split_k<<<dim3(32, 32, NB), dim3(32, 8)>>>(shape_map, XSH, XSL);
    gemm_mma<EPI_TANH, false><<<grid, 256, SMEM_BYTES>>>(W[0], W[1], XSH, XSL, bq, nullptr, nullptr, QH, QL, 0.f);
    // 3..5: wk split, img transpose, GEMM K  <- profiled launch
    split_k<<<MAT / 256, 256>>>(wk, W[2], W[3]);
    transpose_split_k<<<dim3(32, 32, NB), dim3(32, 8)>>>(img_map, XIH, XIL);
    gemm_mma<EPI_TANH, false><<<grid, 256, SMEM_BYTES>>>(W[2], W[3], XIH, XIL, bk, nullptr, nullptr, KH, KL, 0.f);
    // 6..7: wv split, GEMM V (stored transposed [S,C])
    split_k<<<MAT / 256, 256>>>(wv, W[4], W[5]);
    gemm_mma<EPI_TANH_T, false><<<grid, 256, SMEM_BYTES>>>(W[4], W[5], XIH, XIL, bv, nullptr, nullptr, VTH, VTL, 0.f);
    // 8: wc split
    split_k<<<MAT / 256, 256>>>(wc, W[6], W[7]);
    // 9: scores = (Q @ K^T) / 32 -> fp32
    gemm_mma<EPI_SCALE, true><<<grid, 256, SMEM_BYTES>>>(QH, QL, KH, KL, nullptr, nullptr, SF, nullptr, nullptr, 0.03125f);
    // 10: softmax rows -> bf16 hi/lo
    softmax_split_k<<<NB * NC, 256>>>(SF, WAH, WAL);
    // 11: new_v = weights @ V (stored transposed [S,C])
    gemm_mma<EPI_SPLIT_T, true><<<grid, 256, SMEM_BYTES>>>(WAH, WAL, VTH, VTL, nullptr, nullptr, nullptr, NVTH, NVTL, 0.f);
    // 12: out = Wc @ new_v + bc + shape_map
    gemm_mma<EPI_BIASRES, false><<<grid, 256, SMEM_BYTES>>>(W[6], W[7], NVTH, NVTL, bc, shape_map, out, nullptr, nullptr, 0.f);
}